// round 16
// baseline (speedup 1.0000x reference)
#include <cuda_runtime.h>
#include <cuda_bf16.h>
#include <cuda_fp16.h>
#include <cstdint>

#define B_    8
#define S_    1025
#define D_    768
#define H_    12
#define HD_   64
#define M_TOT (B_ * S_)       // 8200
#define M_PAD 8320            // 65 * 128
#define SPAD  1028            // bias row pitch (floats), 16B-aligned

// ---------------------------------------------------------------------------
// Device scratch (fp16 everywhere; X kept as hi/lo split for GEMM accuracy)
// ---------------------------------------------------------------------------
__device__ __align__(128) __half g_qh [(size_t)M_PAD * D_];   // Q * 0.125, fp16
__device__ __align__(128) __half g_kh [(size_t)M_PAD * D_];   // K fp16
__device__ __align__(128) __half g_vh [(size_t)M_PAD * D_];   // V fp16
__device__ __align__(128) __half g_xhi[(size_t)M_PAD * D_];
__device__ __align__(128) __half g_xlo[(size_t)M_PAD * D_];
__device__ __align__(128) __half g_wt [(size_t)3 * D_ * D_];  // W^T fp16 single
__device__ __align__(128) float g_biasp[(size_t)H_ * S_ * SPAD];

// ---------------------------------------------------------------------------
// Base-ISA PTX helpers
// ---------------------------------------------------------------------------
__device__ __forceinline__ uint32_t smem_u32(const void* p) {
    uint32_t a;
    asm("{ .reg .u64 t; cvta.to.shared.u64 t, %1; cvt.u32.u64 %0, t; }"
        : "=r"(a) : "l"(p));
    return a;
}
__device__ __forceinline__ void cp_async16(uint32_t dst, const void* src) {
    asm volatile("cp.async.cg.shared.global [%0], [%1], 16;\n"
                 :: "r"(dst), "l"(src));
}
__device__ __forceinline__ void ldsm4(uint32_t* r, uint32_t addr) {
    asm volatile("ldmatrix.sync.aligned.m8n8.x4.shared.b16 {%0,%1,%2,%3}, [%4];\n"
                 : "=r"(r[0]), "=r"(r[1]), "=r"(r[2]), "=r"(r[3]) : "r"(addr));
}
__device__ __forceinline__ void ldsm4t(uint32_t* r, uint32_t addr) {
    asm volatile("ldmatrix.sync.aligned.m8n8.x4.trans.shared.b16 {%0,%1,%2,%3}, [%4];\n"
                 : "=r"(r[0]), "=r"(r[1]), "=r"(r[2]), "=r"(r[3]) : "r"(addr));
}
__device__ __forceinline__ void mma16816h(float* d, const uint32_t* a,
                                          const uint32_t* b) {
    asm volatile(
        "mma.sync.aligned.m16n8k16.row.col.f32.f16.f16.f32 "
        "{%0,%1,%2,%3}, {%4,%5,%6,%7}, {%8,%9}, {%0,%1,%2,%3};\n"
        : "+f"(d[0]), "+f"(d[1]), "+f"(d[2]), "+f"(d[3])
        : "r"(a[0]), "r"(a[1]), "r"(a[2]), "r"(a[3]), "r"(b[0]), "r"(b[1]));
}
__device__ __forceinline__ uint32_t packh2(float x, float y) {
    __half2 h = __floats2half2_rn(x, y);
    return *(uint32_t*)&h;
}
__device__ __forceinline__ void splith2(float x, float y, uint32_t& hi, uint32_t& lo) {
    __half2 h = __floats2half2_rn(x, y);
    float2 f = __half22float2(h);
    __half2 l = __floats2half2_rn(x - f.x, y - f.y);
    hi = *(uint32_t*)&h;
    lo = *(uint32_t*)&l;
}

// ---------------------------------------------------------------------------
// Conversion: X -> (hi, lo) fp16, rows >= 8200 zeroed (pad to 8320)
// ---------------------------------------------------------------------------
__global__ __launch_bounds__(256) void convx_kernel(const float* __restrict__ X)
{
    size_t i = ((size_t)blockIdx.x * 256 + threadIdx.x) * 4;
    if (i >= (size_t)M_PAD * D_) return;
    size_t m = i / D_;
    float4 x = (m < M_TOT) ? *(const float4*)&X[i] : make_float4(0.f, 0.f, 0.f, 0.f);
    uint2 uh, ul;
    splith2(x.x, x.y, uh.x, ul.x);
    splith2(x.z, x.w, uh.y, ul.y);
    *(uint2*)&g_xhi[i] = uh;
    *(uint2*)&g_xlo[i] = ul;
}

// ---------------------------------------------------------------------------
// Conversion: W^T -> fp16 single, tiled transpose. Wt[n][k] = W[k][n].
// ---------------------------------------------------------------------------
__global__ __launch_bounds__(256) void convw_kernel(
    const float* __restrict__ Wq, const float* __restrict__ Wk,
    const float* __restrict__ Wv)
{
    __shared__ float t[32][33];
    const float* W = (blockIdx.z == 0) ? Wq : (blockIdx.z == 1) ? Wk : Wv;
    __half* oh = g_wt + (size_t)blockIdx.z * D_ * D_;
    int k0 = blockIdx.x * 32, n0 = blockIdx.y * 32;
    for (int i = threadIdx.x; i < 1024; i += 256) {
        int r = i >> 5, c = i & 31;
        t[r][c] = W[(size_t)(k0 + r) * D_ + n0 + c];
    }
    __syncthreads();
    for (int i = threadIdx.x; i < 1024; i += 256) {
        int r = i >> 5, c = i & 31;
        oh[(size_t)(n0 + r) * D_ + k0 + c] = __float2half_rn(t[c][r]);
    }
}

// ---------------------------------------------------------------------------
// Repack rel_bias [H][S][S] -> g_biasp [H][S][SPAD], float4 stores.
// ---------------------------------------------------------------------------
__global__ __launch_bounds__(256) void convb_kernel(const float* __restrict__ rb)
{
    const size_t nrows = (size_t)H_ * S_;
    size_t i = ((size_t)blockIdx.x * 256 + threadIdx.x);
    size_t row = i / (S_ / 4 + 1);
    int cg = (int)(i - row * (S_ / 4 + 1));
    if (row >= nrows) return;
    int col = cg * 4;
    const float* src = rb + row * S_ + col;
    float4 v;
    v.x = (col     < S_) ? src[0] : 0.f;
    v.y = (col + 1 < S_) ? src[1] : 0.f;
    v.z = (col + 2 < S_) ? src[2] : 0.f;
    v.w = (col + 3 < S_) ? src[3] : 0.f;
    *(float4*)&g_biasp[row * SPAD + col] = v;
}

// ---------------------------------------------------------------------------
// fp16 2-MMA GEMM: out = X @ W + b; X split hi/lo fp16, W fp16 single.
// 128 threads, tile 128x64, 2 CTAs/SM. grid = (65, 12, 3).
// Stage (40KB): Ahi 16K | Alo 16K | B 8K. 2 stages = 80KB.
// ---------------------------------------------------------------------------
#define STAGE_BYTES 40960
#define A_LO    16384
#define B_OFF   32768
#define GEMM_SMEM   (2 * STAGE_BYTES)

__global__ __launch_bounds__(128, 2) void gemm_kernel(
    const float* __restrict__ bq, const float* __restrict__ bk,
    const float* __restrict__ bv)
{
    extern __shared__ __align__(1024) unsigned char smg[];
    uint32_t sb = smem_u32(smg);
    int tid = threadIdx.x, wid = tid >> 5, lid = tid & 31;
    int m0 = blockIdx.x * 128;
    int n0 = blockIdx.y * 64;
    int mat = blockIdx.z;

    const __half* Bw = g_wt + (size_t)mat * D_ * D_;
    __half* outp = (mat == 0) ? g_qh : (mat == 1) ? g_kh : g_vh;
    const float* bias = (mat == 0) ? bq : (mat == 1) ? bk : bv;
    const float osc = (mat == 0) ? 0.125f : 1.0f;

    float acc[2][8][4];
#pragma unroll
    for (int f = 0; f < 2; f++)
#pragma unroll
        for (int nf = 0; nf < 8; nf++)
#pragma unroll
            for (int j = 0; j < 4; j++) acc[f][nf][j] = 0.f;

    auto load_stage = [&](int c, int s) {
        int k0 = c * 64;
        uint32_t st = sb + s * STAGE_BYTES;
        // A: 2 splits x 128 rows x 8 chunks = 2048 chunks
#pragma unroll
        for (int pass = 0; pass < 16; pass++) {
            int idx = pass * 128 + tid;
            int sp = idx >> 10, rem = idx & 1023;
            int row = rem >> 3, cc = rem & 7;
            const __half* src =
                (sp ? g_xlo : g_xhi) + (size_t)(m0 + row) * D_ + k0 + cc * 8;
            cp_async16(st + sp * A_LO + row * 128 + ((cc ^ (row & 7)) << 4), src);
        }
        // B: 64 rows x 8 chunks = 512 chunks
#pragma unroll
        for (int pass = 0; pass < 4; pass++) {
            int idx = pass * 128 + tid;
            int row = idx >> 3, cc = idx & 7;
            const __half* src = Bw + (size_t)(n0 + row) * D_ + k0 + cc * 8;
            cp_async16(st + B_OFF + row * 128 + ((cc ^ (row & 7)) << 4), src);
        }
        asm volatile("cp.async.commit_group;\n" ::: "memory");
    };

    load_stage(0, 0);

    for (int c = 0; c < 12; c++) {
        int s = c & 1;
        if (c + 1 < 12) {
            load_stage(c + 1, s ^ 1);
            asm volatile("cp.async.wait_group 1;\n" ::: "memory");
        } else {
            asm volatile("cp.async.wait_group 0;\n" ::: "memory");
        }
        __syncthreads();

        uint32_t st  = sb + s * STAGE_BYTES;
        uint32_t bB  = st + B_OFF;
        int q = lid >> 3, r = lid & 7;

#pragma unroll
        for (int ks = 0; ks < 4; ks++) {
            uint32_t ah[2][4], alr[2][4];
#pragma unroll
            for (int f = 0; f < 2; f++) {
                int mrow = wid * 32 + f * 16 + (q & 1) * 8 + r;
                int cc   = ks * 2 + (q >> 1);
                uint32_t addr = st + mrow * 128 + ((cc ^ (mrow & 7)) << 4);
                ldsm4(ah[f], addr);
                ldsm4(alr[f], addr + A_LO);
            }
            uint32_t bb[8][2];
#pragma unroll
            for (int g = 0; g < 4; g++) {
                int nrow = g * 16 + (q >> 1) * 8 + r;
                int cc   = ks * 2 + (q & 1);
                uint32_t t[4];
                ldsm4(t, bB + nrow * 128 + ((cc ^ (nrow & 7)) << 4));
                bb[2 * g][0] = t[0]; bb[2 * g][1] = t[1];
                bb[2 * g + 1][0] = t[2]; bb[2 * g + 1][1] = t[3];
            }
#pragma unroll
            for (int f = 0; f < 2; f++)
#pragma unroll
                for (int nf = 0; nf < 8; nf++) {
                    mma16816h(acc[f][nf], ah[f], bb[nf]);
                    mma16816h(acc[f][nf], alr[f], bb[nf]);
                }
        }
        __syncthreads();
    }

    // ---- epilogue: + bias, (x0.125 for Q), pack fp16 ----
    int g2 = lid >> 2, tg = lid & 3;
    int mbase = m0 + wid * 32;
#pragma unroll
    for (int f = 0; f < 2; f++) {
#pragma unroll
        for (int nf = 0; nf < 8; nf++) {
            int n = n0 + nf * 8 + tg * 2;
            float b0 = bias[n], b1 = bias[n + 1];
            int m = mbase + f * 16 + g2;
            if (m < M_TOT) {
                uint32_t hv = packh2((acc[f][nf][0] + b0) * osc,
                                     (acc[f][nf][1] + b1) * osc);
                *(uint32_t*)&outp[(size_t)m * D_ + n] = hv;
            }
            if (m + 8 < M_TOT) {
                uint32_t hv = packh2((acc[f][nf][2] + b0) * osc,
                                     (acc[f][nf][3] + b1) * osc);
                *(uint32_t*)&outp[(size_t)(m + 8) * D_ + n] = hv;
            }
        }
    }
}

// ---------------------------------------------------------------------------
// Tensor-core flash attention, all-fp16 MMA path.
// QK: 1 fp16 MMA (Q fp16 single pre-scaled, K fp16 single).
// PV: 1 fp16 MMA (validated R15). Bias prefetched fp32.
// Stage (33KB): K 8K | V 8K | bias 64*272B.
// ---------------------------------------------------------------------------
#define QT   64
#define NKT  17
#define BIAS_OFF 16384
#define KVST (16384 + 64 * 272)          // 33792 per stage
#define ATT_SMEM (2 * KVST)              // 67584

__global__ __launch_bounds__(128, 2) void attn_kernel(float* __restrict__ out)
{
    extern __shared__ __align__(1024) unsigned char sma[];
    uint32_t sb = smem_u32(sma);
    int tid = threadIdx.x, wid = tid >> 5, lid = tid & 31;
    int qq = lid >> 3, r = lid & 7;
    int g  = lid >> 2, t = lid & 3;
    int q0 = blockIdx.x * QT;
    int b  = blockIdx.y;
    int h  = blockIdx.z;

    const __half* arrp[2] = {g_kh, g_vh};

    auto load_q = [&]() {
#pragma unroll
        for (int p = 0; p < 4; p++) {
            int idx = p * 128 + tid;                 // 512 chunks
            int row = idx >> 3, cc = idx & 7;
            int gq = q0 + row; if (gq > S_ - 1) gq = S_ - 1;
            const __half* src = g_qh
                + (size_t)(b * S_ + gq) * D_ + h * HD_ + cc * 8;
            cp_async16(sb + row * 128 + ((cc ^ (row & 7)) << 4), src);
        }
        asm volatile("cp.async.commit_group;\n" ::: "memory");
    };
    auto load_kv = [&](int kt, int s) {
#pragma unroll
        for (int p = 0; p < 8; p++) {
            int idx = p * 128 + tid;                 // 1024 chunks (K, V)
            int a = idx >> 9, rem = idx & 511;
            int row = rem >> 3, cc = rem & 7;
            int gk = kt * 64 + row; if (gk > S_ - 1) gk = S_ - 1;
            const __half* src = arrp[a]
                + (size_t)(b * S_ + gk) * D_ + h * HD_ + cc * 8;
            cp_async16(sb + s * KVST + a * 8192 + row * 128 + ((cc ^ (row & 7)) << 4), src);
        }
        // bias tile: 64 q-rows x 64 keys fp32 from padded buffer
#pragma unroll
        for (int p = 0; p < 8; p++) {
            int idx = p * 128 + tid;                 // 1024 chunks
            int row = idx >> 4, cc = idx & 15;
            int gq = q0 + row; if (gq > S_ - 1) gq = S_ - 1;
            int kc = kt * 64 + cc * 4;
            const float* src = g_biasp + ((size_t)h * S_ + gq) * SPAD + kc;
            cp_async16(sb + s * KVST + BIAS_OFF + row * 272 + cc * 16, src);
        }
        asm volatile("cp.async.commit_group;\n" ::: "memory");
    };

    load_q();
    load_kv(0, 1);
    asm volatile("cp.async.wait_group 1;\n" ::: "memory");
    __syncthreads();

    // Extract Q A-fragments to registers.
    uint32_t qh[4][4];
#pragma unroll
    for (int ks = 0; ks < 4; ks++) {
        int mrow = wid * 16 + (qq & 1) * 8 + r;
        int cc = ks * 2 + (qq >> 1);
        ldsm4(qh[ks], sb + mrow * 128 + ((cc ^ (mrow & 7)) << 4));
    }
    __syncthreads();    // stage-0 region now reusable for KV

    float o[8][4];
#pragma unroll
    for (int nt = 0; nt < 8; nt++)
#pragma unroll
        for (int j = 0; j < 4; j++) o[nt][j] = 0.f;
    float rm0 = -1e30f, rm1 = -1e30f, rl0 = 0.f, rl1 = 0.f;

    int rq0 = q0 + wid * 16 + g;
    int rq1 = rq0 + 8;

    for (int it = 0; it < NKT; it++) {
        int s = (it + 1) & 1;
        __syncthreads();
        if (it + 1 < NKT) {
            load_kv(it + 1, s ^ 1);
            asm volatile("cp.async.wait_group 1;\n" ::: "memory");
        } else {
            asm volatile("cp.async.wait_group 0;\n" ::: "memory");
        }
        __syncthreads();

        uint32_t kb = sb + s * KVST;
        float sc[8][4];
#pragma unroll
        for (int nt = 0; nt < 8; nt++)
#pragma unroll
            for (int j = 0; j < 4; j++) sc[nt][j] = 0.f;

        // ---- S = Q' K^T (1 fp16 MMA per frag pair) ----
#pragma unroll
        for (int ks = 0; ks < 4; ks++) {
            uint32_t bf[8][2];
#pragma unroll
            for (int gg = 0; gg < 4; gg++) {
                int nrow = gg * 16 + (qq >> 1) * 8 + r;
                int cc = ks * 2 + (qq & 1);
                uint32_t tt[4];
                ldsm4(tt, kb + nrow * 128 + ((cc ^ (nrow & 7)) << 4));
                bf[2 * gg][0] = tt[0]; bf[2 * gg][1] = tt[1];
                bf[2 * gg + 1][0] = tt[2]; bf[2 * gg + 1][1] = tt[3];
            }
#pragma unroll
            for (int nt = 0; nt < 8; nt++)
                mma16816h(sc[nt], qh[ks], bf[nt]);
        }

        // ---- bias (from smem) + mask + online softmax ----
        const float* bsm = (const float*)(sma + s * KVST + BIAS_OFF);
        const float* br0 = bsm + (wid * 16 + g) * 68 + 2 * t;
        const float* br1 = br0 + 8 * 68;
        int kbase = it * 64;
        float nx0 = rm0, nx1 = rm1;
#pragma unroll
        for (int nt = 0; nt < 8; nt++) {
            int kc = kbase + nt * 8 + 2 * t;
            bool v0 = kc < S_, v1 = (kc + 1) < S_;
            float2 b0 = *(const float2*)(br0 + nt * 8);
            float2 b1 = *(const float2*)(br1 + nt * 8);
            sc[nt][0] = v0 ? sc[nt][0] + b0.x : -1e30f;
            sc[nt][1] = v1 ? sc[nt][1] + b0.y : -1e30f;
            sc[nt][2] = v0 ? sc[nt][2] + b1.x : -1e30f;
            sc[nt][3] = v1 ? sc[nt][3] + b1.y : -1e30f;
            nx0 = fmaxf(nx0, fmaxf(sc[nt][0], sc[nt][1]));
            nx1 = fmaxf(nx1, fmaxf(sc[nt][2], sc[nt][3]));
        }
        nx0 = fmaxf(nx0, __shfl_xor_sync(0xffffffffu, nx0, 1));
        nx0 = fmaxf(nx0, __shfl_xor_sync(0xffffffffu, nx0, 2));
        nx1 = fmaxf(nx1, __shfl_xor_sync(0xffffffffu, nx1, 1));
        nx1 = fmaxf(nx1, __shfl_xor_sync(0xffffffffu, nx1, 2));
        float a0 = __expf(rm0 - nx0), a1 = __expf(rm1 - nx1);
        rm0 = nx0; rm1 = nx1;
        float s0 = 0.f, s1 = 0.f;
#pragma unroll
        for (int nt = 0; nt < 8; nt++) {
            sc[nt][0] = __expf(sc[nt][0] - nx0);
            sc[nt][1] = __expf(sc[nt][1] - nx0);
            sc[nt][2] = __expf(sc[nt][2] - nx1);
            sc[nt][3] = __expf(sc[nt][3] - nx1);
            s0 += sc[nt][0] + sc[nt][1];
            s1 += sc[nt][2] + sc[nt][3];
        }
        s0 += __shfl_xor_sync(0xffffffffu, s0, 1);
        s0 += __shfl_xor_sync(0xffffffffu, s0, 2);
        s1 += __shfl_xor_sync(0xffffffffu, s1, 1);
        s1 += __shfl_xor_sync(0xffffffffu, s1, 2);
        rl0 = rl0 * a0 + s0;
        rl1 = rl1 * a1 + s1;
#pragma unroll
        for (int nt = 0; nt < 8; nt++) {
            o[nt][0] *= a0; o[nt][1] *= a0; o[nt][2] *= a1; o[nt][3] *= a1;
        }

        // ---- O += P V (single fp16 MMA pass) ----
        uint32_t vb = kb + 8192;
#pragma unroll
        for (int ks = 0; ks < 4; ks++) {
            uint32_t ph[4];
            ph[0] = packh2(sc[2 * ks][0],     sc[2 * ks][1]);
            ph[1] = packh2(sc[2 * ks][2],     sc[2 * ks][3]);
            ph[2] = packh2(sc[2 * ks + 1][0], sc[2 * ks + 1][1]);
            ph[3] = packh2(sc[2 * ks + 1][2], sc[2 * ks + 1][3]);

            uint32_t bf[8][2];
#pragma unroll
            for (int dp = 0; dp < 4; dp++) {
                int row = ks * 16 + (qq & 1) * 8 + r;
                int cc = dp * 2 + (qq >> 1);
                uint32_t tt[4];
                ldsm4t(tt, vb + row * 128 + ((cc ^ (row & 7)) << 4));
                bf[2 * dp][0] = tt[0]; bf[2 * dp][1] = tt[1];
                bf[2 * dp + 1][0] = tt[2]; bf[2 * dp + 1][1] = tt[3];
            }
#pragma unroll
            for (int nt = 0; nt < 8; nt++)
                mma16816h(o[nt], ph, bf[nt]);
        }
    }

    // ---- finalize + store ----
    float i0 = 1.f / rl0, i1 = 1.f / rl1;
#pragma unroll
    for (int nt = 0; nt < 8; nt++) {
        int dc = h * HD_ + nt * 8 + 2 * t;
        if (rq0 < S_)
            *(float2*)&out[((size_t)b * S_ + rq0) * D_ + dc] =
                make_float2(o[nt][0] * i0, o[nt][1] * i0);
        if (rq1 < S_)
            *(float2*)&out[((size_t)b * S_ + rq1) * D_ + dc] =
                make_float2(o[nt][2] * i1, o[nt][3] * i1);
    }
}

// ---------------------------------------------------------------------------
extern "C" void kernel_launch(void* const* d_in, const int* in_sizes, int n_in,
                              void* d_out, int out_size)
{
    const float* hidden = (const float*)d_in[0];
    const float* bias   = (const float*)d_in[1];
    const float* Wq     = (const float*)d_in[2];
    const float* bq     = (const float*)d_in[3];
    const float* Wk     = (const float*)d_in[4];
    const float* bk     = (const float*)d_in[5];
    const float* Wv     = (const float*)d_in[6];
    const float* bv     = (const float*)d_in[7];
    float* out = (float*)d_out;

    cudaFuncSetAttribute(gemm_kernel,
                         cudaFuncAttributeMaxDynamicSharedMemorySize, GEMM_SMEM);
    cudaFuncSetAttribute(attn_kernel,
                         cudaFuncAttributeMaxDynamicSharedMemorySize, ATT_SMEM);

    convx_kernel<<<(M_PAD * D_ / 4 + 255) / 256, 256>>>(hidden);
    convw_kernel<<<dim3(24, 24, 3), 256>>>(Wq, Wk, Wv);
    {
        size_t tot = (size_t)H_ * S_ * (S_ / 4 + 1);
        convb_kernel<<<(unsigned)((tot + 255) / 256), 256>>>(bias);
    }
    gemm_kernel<<<dim3(65, 12, 3), 128, GEMM_SMEM>>>(bq, bk, bv);

    dim3 g2((S_ + QT - 1) / QT, B_, H_);   // (17, 8, 12)
    attn_kernel<<<g2, 128, ATT_SMEM>>>(out);
}

// round 17
// speedup vs baseline: 1.2692x; 1.2692x over previous
#include <cuda_runtime.h>
#include <cuda_bf16.h>
#include <cuda_fp16.h>
#include <cstdint>

#define B_    8
#define S_    1025
#define D_    768
#define H_    12
#define HD_   64
#define M_TOT (B_ * S_)       // 8200
#define M_PAD 8320            // 65 * 128
#define SPAD  1028            // bias row pitch (floats), 16B-aligned

// ---------------------------------------------------------------------------
// Device scratch
// ---------------------------------------------------------------------------
__device__ __align__(128) __nv_bfloat16 g_qhi[(size_t)M_PAD * D_];
__device__ __align__(128) __nv_bfloat16 g_qlo[(size_t)M_PAD * D_];
__device__ __align__(128) __nv_bfloat16 g_khi[(size_t)M_PAD * D_];
__device__ __align__(128) __nv_bfloat16 g_klo[(size_t)M_PAD * D_];  // written, unused by attn
__device__ __align__(128) __half        g_vh [(size_t)M_PAD * D_];  // V fp16
__device__ __align__(128) __nv_bfloat16 g_xhi[(size_t)M_PAD * D_];
__device__ __align__(128) __nv_bfloat16 g_xlo[(size_t)M_PAD * D_];
__device__ __align__(128) __nv_bfloat16 g_wthi[(size_t)3 * D_ * D_];
__device__ __align__(128) __nv_bfloat16 g_wtlo[(size_t)3 * D_ * D_];
__device__ __align__(128) float g_biasp[(size_t)H_ * S_ * SPAD];

// ---------------------------------------------------------------------------
// Base-ISA PTX helpers
// ---------------------------------------------------------------------------
__device__ __forceinline__ uint32_t smem_u32(const void* p) {
    uint32_t a;
    asm("{ .reg .u64 t; cvta.to.shared.u64 t, %1; cvt.u32.u64 %0, t; }"
        : "=r"(a) : "l"(p));
    return a;
}
__device__ __forceinline__ void cp_async16(uint32_t dst, const void* src) {
    asm volatile("cp.async.cg.shared.global [%0], [%1], 16;\n"
                 :: "r"(dst), "l"(src));
}
__device__ __forceinline__ void ldsm4(uint32_t* r, uint32_t addr) {
    asm volatile("ldmatrix.sync.aligned.m8n8.x4.shared.b16 {%0,%1,%2,%3}, [%4];\n"
                 : "=r"(r[0]), "=r"(r[1]), "=r"(r[2]), "=r"(r[3]) : "r"(addr));
}
__device__ __forceinline__ void ldsm4t(uint32_t* r, uint32_t addr) {
    asm volatile("ldmatrix.sync.aligned.m8n8.x4.trans.shared.b16 {%0,%1,%2,%3}, [%4];\n"
                 : "=r"(r[0]), "=r"(r[1]), "=r"(r[2]), "=r"(r[3]) : "r"(addr));
}
__device__ __forceinline__ void mma16816(float* d, const uint32_t* a,
                                         const uint32_t* b) {
    asm volatile(
        "mma.sync.aligned.m16n8k16.row.col.f32.bf16.bf16.f32 "
        "{%0,%1,%2,%3}, {%4,%5,%6,%7}, {%8,%9}, {%0,%1,%2,%3};\n"
        : "+f"(d[0]), "+f"(d[1]), "+f"(d[2]), "+f"(d[3])
        : "r"(a[0]), "r"(a[1]), "r"(a[2]), "r"(a[3]), "r"(b[0]), "r"(b[1]));
}
__device__ __forceinline__ void mma16816h(float* d, const uint32_t* a,
                                          const uint32_t* b) {
    asm volatile(
        "mma.sync.aligned.m16n8k16.row.col.f32.f16.f16.f32 "
        "{%0,%1,%2,%3}, {%4,%5,%6,%7}, {%8,%9}, {%0,%1,%2,%3};\n"
        : "+f"(d[0]), "+f"(d[1]), "+f"(d[2]), "+f"(d[3])
        : "r"(a[0]), "r"(a[1]), "r"(a[2]), "r"(a[3]), "r"(b[0]), "r"(b[1]));
}
__device__ __forceinline__ void split2(float x, float y, uint32_t& hi, uint32_t& lo) {
    __nv_bfloat162 h = __floats2bfloat162_rn(x, y);
    float2 f = __bfloat1622float2(h);
    __nv_bfloat162 l = __floats2bfloat162_rn(x - f.x, y - f.y);
    hi = *(uint32_t*)&h;
    lo = *(uint32_t*)&l;
}
__device__ __forceinline__ uint32_t packh2(float x, float y) {
    __half2 h = __floats2half2_rn(x, y);
    return *(uint32_t*)&h;
}

// ---------------------------------------------------------------------------
// Conversion: X -> (hi, lo) bf16, rows >= 8200 zeroed (pad to 8320)
// ---------------------------------------------------------------------------
__global__ __launch_bounds__(256) void convx_kernel(const float* __restrict__ X)
{
    size_t i = ((size_t)blockIdx.x * 256 + threadIdx.x) * 4;
    if (i >= (size_t)M_PAD * D_) return;
    size_t m = i / D_;
    float4 x = (m < M_TOT) ? *(const float4*)&X[i] : make_float4(0.f, 0.f, 0.f, 0.f);
    uint2 uh, ul;
    split2(x.x, x.y, uh.x, ul.x);
    split2(x.z, x.w, uh.y, ul.y);
    *(uint2*)&g_xhi[i] = uh;
    *(uint2*)&g_xlo[i] = ul;
}

// ---------------------------------------------------------------------------
// Conversion: W^T -> (hi, lo) bf16, tiled transpose. Wt[n][k] = W[k][n].
// ---------------------------------------------------------------------------
__global__ __launch_bounds__(256) void convw_kernel(
    const float* __restrict__ Wq, const float* __restrict__ Wk,
    const float* __restrict__ Wv)
{
    __shared__ float t[32][33];
    const float* W = (blockIdx.z == 0) ? Wq : (blockIdx.z == 1) ? Wk : Wv;
    __nv_bfloat16* oh = g_wthi + (size_t)blockIdx.z * D_ * D_;
    __nv_bfloat16* ol = g_wtlo + (size_t)blockIdx.z * D_ * D_;
    int k0 = blockIdx.x * 32, n0 = blockIdx.y * 32;
    for (int i = threadIdx.x; i < 1024; i += 256) {
        int r = i >> 5, c = i & 31;
        t[r][c] = W[(size_t)(k0 + r) * D_ + n0 + c];
    }
    __syncthreads();
    for (int i = threadIdx.x; i < 1024; i += 256) {
        int r = i >> 5, c = i & 31;
        float x = t[c][r];
        __nv_bfloat16 h = __float2bfloat16(x);
        oh[(size_t)(n0 + r) * D_ + k0 + c] = h;
        ol[(size_t)(n0 + r) * D_ + k0 + c] =
            __float2bfloat16(x - __bfloat162float(h));
    }
}

// ---------------------------------------------------------------------------
// Repack rel_bias [H][S][S] -> g_biasp [H][S][SPAD], float4 stores.
// ---------------------------------------------------------------------------
__global__ __launch_bounds__(256) void convb_kernel(const float* __restrict__ rb)
{
    const size_t nrows = (size_t)H_ * S_;
    size_t i = ((size_t)blockIdx.x * 256 + threadIdx.x);
    size_t row = i / (S_ / 4 + 1);
    int cg = (int)(i - row * (S_ / 4 + 1));
    if (row >= nrows) return;
    int col = cg * 4;
    const float* src = rb + row * S_ + col;
    float4 v;
    v.x = (col     < S_) ? src[0] : 0.f;
    v.y = (col + 1 < S_) ? src[1] : 0.f;
    v.z = (col + 2 < S_) ? src[2] : 0.f;
    v.w = (col + 3 < S_) ? src[3] : 0.f;
    *(float4*)&g_biasp[row * SPAD + col] = v;
}

// ---------------------------------------------------------------------------
// mma.sync split-bf16 GEMM (R15 config, validated at 202us): 128 threads,
// tile 128x64, 2 CTAs/SM. Epilogue: Q/K -> bf16 hi/lo (Q x0.125); V -> fp16.
// ---------------------------------------------------------------------------
#define STAGE_BYTES 49152
#define A_LO    16384
#define B_OFF   32768
#define B_LO    8192
#define GEMM_SMEM   (2 * STAGE_BYTES)

__global__ __launch_bounds__(128, 2) void gemm_kernel(
    const float* __restrict__ bq, const float* __restrict__ bk,
    const float* __restrict__ bv)
{
    extern __shared__ __align__(1024) unsigned char smg[];
    uint32_t sb = smem_u32(smg);
    int tid = threadIdx.x, wid = tid >> 5, lid = tid & 31;
    int m0 = blockIdx.x * 128;
    int n0 = blockIdx.y * 64;
    int mat = blockIdx.z;

    const __nv_bfloat16* Bhi = g_wthi + (size_t)mat * D_ * D_;
    const __nv_bfloat16* Blo = g_wtlo + (size_t)mat * D_ * D_;
    __nv_bfloat16* ohi = (mat == 0) ? g_qhi : g_khi;
    __nv_bfloat16* olo = (mat == 0) ? g_qlo : g_klo;
    const float* bias = (mat == 0) ? bq : (mat == 1) ? bk : bv;
    const float osc = (mat == 0) ? 0.125f : 1.0f;

    float acc[2][8][4];
#pragma unroll
    for (int f = 0; f < 2; f++)
#pragma unroll
        for (int nf = 0; nf < 8; nf++)
#pragma unroll
            for (int j = 0; j < 4; j++) acc[f][nf][j] = 0.f;

    auto load_stage = [&](int c, int s) {
        int k0 = c * 64;
        uint32_t st = sb + s * STAGE_BYTES;
#pragma unroll
        for (int pass = 0; pass < 16; pass++) {
            int idx = pass * 128 + tid;
            int sp = idx >> 10, rem = idx & 1023;
            int row = rem >> 3, cc = rem & 7;
            const __nv_bfloat16* src =
                (sp ? g_xlo : g_xhi) + (size_t)(m0 + row) * D_ + k0 + cc * 8;
            cp_async16(st + sp * A_LO + row * 128 + ((cc ^ (row & 7)) << 4), src);
        }
#pragma unroll
        for (int pass = 0; pass < 8; pass++) {
            int idx = pass * 128 + tid;
            int sp = idx >> 9, rem = idx & 511;
            int row = rem >> 3, cc = rem & 7;
            const __nv_bfloat16* src =
                (sp ? Blo : Bhi) + (size_t)(n0 + row) * D_ + k0 + cc * 8;
            cp_async16(st + B_OFF + sp * B_LO + row * 128 + ((cc ^ (row & 7)) << 4), src);
        }
        asm volatile("cp.async.commit_group;\n" ::: "memory");
    };

    load_stage(0, 0);

    for (int c = 0; c < 12; c++) {
        int s = c & 1;
        if (c + 1 < 12) {
            load_stage(c + 1, s ^ 1);
            asm volatile("cp.async.wait_group 1;\n" ::: "memory");
        } else {
            asm volatile("cp.async.wait_group 0;\n" ::: "memory");
        }
        __syncthreads();

        uint32_t st  = sb + s * STAGE_BYTES;
        uint32_t bB  = st + B_OFF;
        int q = lid >> 3, r = lid & 7;

#pragma unroll
        for (int ks = 0; ks < 4; ks++) {
            uint32_t ah[2][4], alr[2][4];
#pragma unroll
            for (int f = 0; f < 2; f++) {
                int mrow = wid * 32 + f * 16 + (q & 1) * 8 + r;
                int cc   = ks * 2 + (q >> 1);
                uint32_t addr = st + mrow * 128 + ((cc ^ (mrow & 7)) << 4);
                ldsm4(ah[f], addr);
                ldsm4(alr[f], addr + A_LO);
            }
            uint32_t bb[8][2];
#pragma unroll
            for (int g = 0; g < 4; g++) {
                int nrow = g * 16 + (q >> 1) * 8 + r;
                int cc   = ks * 2 + (q & 1);
                uint32_t t[4];
                ldsm4(t, bB + nrow * 128 + ((cc ^ (nrow & 7)) << 4));
                bb[2 * g][0] = t[0]; bb[2 * g][1] = t[1];
                bb[2 * g + 1][0] = t[2]; bb[2 * g + 1][1] = t[3];
            }
#pragma unroll
            for (int f = 0; f < 2; f++)
#pragma unroll
                for (int nf = 0; nf < 8; nf++) {
                    mma16816(acc[f][nf], ah[f], bb[nf]);
                    mma16816(acc[f][nf], alr[f], bb[nf]);
                }
#pragma unroll
            for (int g = 0; g < 4; g++) {
                int nrow = g * 16 + (q >> 1) * 8 + r;
                int cc   = ks * 2 + (q & 1);
                uint32_t t[4];
                ldsm4(t, bB + B_LO + nrow * 128 + ((cc ^ (nrow & 7)) << 4));
                bb[2 * g][0] = t[0]; bb[2 * g][1] = t[1];
                bb[2 * g + 1][0] = t[2]; bb[2 * g + 1][1] = t[3];
            }
#pragma unroll
            for (int f = 0; f < 2; f++)
#pragma unroll
                for (int nf = 0; nf < 8; nf++)
                    mma16816(acc[f][nf], ah[f], bb[nf]);
        }
        __syncthreads();
    }

    // ---- epilogue ----
    int g2 = lid >> 2, tg = lid & 3;
    int mbase = m0 + wid * 32;
#pragma unroll
    for (int f = 0; f < 2; f++) {
#pragma unroll
        for (int nf = 0; nf < 8; nf++) {
            int n = n0 + nf * 8 + tg * 2;
            float b0 = bias[n], b1 = bias[n + 1];
            int m = mbase + f * 16 + g2;
            if (m < M_TOT) {
                float x0 = acc[f][nf][0] + b0, x1 = acc[f][nf][1] + b1;
                if (mat == 2) {
                    uint32_t hv = packh2(x0, x1);
                    *(uint32_t*)&g_vh[(size_t)m * D_ + n] = hv;
                } else {
                    uint32_t h, l;
                    split2(x0 * osc, x1 * osc, h, l);
                    *(uint32_t*)&ohi[(size_t)m * D_ + n] = h;
                    *(uint32_t*)&olo[(size_t)m * D_ + n] = l;
                }
            }
            if (m + 8 < M_TOT) {
                float x0 = acc[f][nf][2] + b0, x1 = acc[f][nf][3] + b1;
                if (mat == 2) {
                    uint32_t hv = packh2(x0, x1);
                    *(uint32_t*)&g_vh[(size_t)(m + 8) * D_ + n] = hv;
                } else {
                    uint32_t h, l;
                    split2(x0 * osc, x1 * osc, h, l);
                    *(uint32_t*)&ohi[(size_t)(m + 8) * D_ + n] = h;
                    *(uint32_t*)&olo[(size_t)(m + 8) * D_ + n] = l;
                }
            }
        }
    }
}

// ---------------------------------------------------------------------------
// Tensor-core flash attention. R17: QK = 2 bf16 MMAs (Q split hi/lo, K bf16
// SINGLE — Klo not loaded). PV = 1 fp16 MMA (validated R15).
// Stage (33KB): K 8K | Vfp16 8K | bias 64*272B.
// ---------------------------------------------------------------------------
#define QT   64
#define NKT  17
#define BIAS_OFF 16384
#define KVST (16384 + 64 * 272)          // 33792 per stage
#define ATT_SMEM (2 * KVST)              // 67584

__global__ __launch_bounds__(128, 2) void attn_kernel(float* __restrict__ out)
{
    extern __shared__ __align__(1024) unsigned char sma[];
    uint32_t sb = smem_u32(sma);
    int tid = threadIdx.x, wid = tid >> 5, lid = tid & 31;
    int qq = lid >> 3, r = lid & 7;
    int g  = lid >> 2, t = lid & 3;
    int q0 = blockIdx.x * QT;
    int b  = blockIdx.y;
    int h  = blockIdx.z;

    const __nv_bfloat16* arrp[2] = {g_khi, (const __nv_bfloat16*)g_vh};

    auto load_q = [&]() {
#pragma unroll
        for (int p = 0; p < 8; p++) {
            int idx = p * 128 + tid;                 // 1024 chunks (Qhi, Qlo)
            int sp = idx >> 9, rem = idx & 511;
            int row = rem >> 3, cc = rem & 7;
            int gq = q0 + row; if (gq > S_ - 1) gq = S_ - 1;
            const __nv_bfloat16* src = (sp ? g_qlo : g_qhi)
                + (size_t)(b * S_ + gq) * D_ + h * HD_ + cc * 8;
            cp_async16(sb + sp * 8192 + row * 128 + ((cc ^ (row & 7)) << 4), src);
        }
        asm volatile("cp.async.commit_group;\n" ::: "memory");
    };
    auto load_kv = [&](int kt, int s) {
#pragma unroll
        for (int p = 0; p < 8; p++) {
            int idx = p * 128 + tid;                 // 1024 chunks (K, V)
            int a = idx >> 9, rem = idx & 511;
            int row = rem >> 3, cc = rem & 7;
            int gk = kt * 64 + row; if (gk > S_ - 1) gk = S_ - 1;
            const __nv_bfloat16* src = arrp[a]
                + (size_t)(b * S_ + gk) * D_ + h * HD_ + cc * 8;
            cp_async16(sb + s * KVST + a * 8192 + row * 128 + ((cc ^ (row & 7)) << 4), src);
        }
        // bias tile: 64 q-rows x 64 keys fp32 from padded buffer
#pragma unroll
        for (int p = 0; p < 8; p++) {
            int idx = p * 128 + tid;                 // 1024 chunks
            int row = idx >> 4, cc = idx & 15;
            int gq = q0 + row; if (gq > S_ - 1) gq = S_ - 1;
            int kc = kt * 64 + cc * 4;
            const float* src = g_biasp + ((size_t)h * S_ + gq) * SPAD + kc;
            cp_async16(sb + s * KVST + BIAS_OFF + row * 272 + cc * 16, src);
        }
        asm volatile("cp.async.commit_group;\n" ::: "memory");
    };

    load_q();
    load_kv(0, 1);
    asm volatile("cp.async.wait_group 1;\n" ::: "memory");
    __syncthreads();

    // Extract Q A-fragments (hi+lo) to registers.
    uint32_t qh[4][4], qlr[4][4];
#pragma unroll
    for (int ks = 0; ks < 4; ks++) {
        int mrow = wid * 16 + (qq & 1) * 8 + r;
        int cc = ks * 2 + (qq >> 1);
        uint32_t addr = sb + mrow * 128 + ((cc ^ (mrow & 7)) << 4);
        ldsm4(qh[ks], addr);
        ldsm4(qlr[ks], addr + 8192);
    }
    __syncthreads();    // stage-0 region now reusable for KV

    float o[8][4];
#pragma unroll
    for (int nt = 0; nt < 8; nt++)
#pragma unroll
        for (int j = 0; j < 4; j++) o[nt][j] = 0.f;
    float rm0 = -1e30f, rm1 = -1e30f, rl0 = 0.f, rl1 = 0.f;

    int rq0 = q0 + wid * 16 + g;
    int rq1 = rq0 + 8;

    for (int it = 0; it < NKT; it++) {
        int s = (it + 1) & 1;
        __syncthreads();
        if (it + 1 < NKT) {
            load_kv(it + 1, s ^ 1);
            asm volatile("cp.async.wait_group 1;\n" ::: "memory");
        } else {
            asm volatile("cp.async.wait_group 0;\n" ::: "memory");
        }
        __syncthreads();

        uint32_t kb = sb + s * KVST;
        float sc[8][4];
#pragma unroll
        for (int nt = 0; nt < 8; nt++)
#pragma unroll
            for (int j = 0; j < 4; j++) sc[nt][j] = 0.f;

        // ---- S = Q' K^T (2 bf16 MMAs: Qh.K + Ql.K) ----
#pragma unroll
        for (int ks = 0; ks < 4; ks++) {
            uint32_t bf[8][2];
#pragma unroll
            for (int gg = 0; gg < 4; gg++) {
                int nrow = gg * 16 + (qq >> 1) * 8 + r;
                int cc = ks * 2 + (qq & 1);
                uint32_t tt[4];
                ldsm4(tt, kb + nrow * 128 + ((cc ^ (nrow & 7)) << 4));
                bf[2 * gg][0] = tt[0]; bf[2 * gg][1] = tt[1];
                bf[2 * gg + 1][0] = tt[2]; bf[2 * gg + 1][1] = tt[3];
            }
#pragma unroll
            for (int nt = 0; nt < 8; nt++) {
                mma16816(sc[nt], qh[ks], bf[nt]);
                mma16816(sc[nt], qlr[ks], bf[nt]);
            }
        }

        // ---- bias (from smem) + mask + online softmax ----
        const float* bsm = (const float*)(sma + s * KVST + BIAS_OFF);
        const float* br0 = bsm + (wid * 16 + g) * 68 + 2 * t;
        const float* br1 = br0 + 8 * 68;
        int kbase = it * 64;
        float nx0 = rm0, nx1 = rm1;
#pragma unroll
        for (int nt = 0; nt < 8; nt++) {
            int kc = kbase + nt * 8 + 2 * t;
            bool v0 = kc < S_, v1 = (kc + 1) < S_;
            float2 b0 = *(const float2*)(br0 + nt * 8);
            float2 b1 = *(const float2*)(br1 + nt * 8);
            sc[nt][0] = v0 ? sc[nt][0] + b0.x : -1e30f;
            sc[nt][1] = v1 ? sc[nt][1] + b0.y : -1e30f;
            sc[nt][2] = v0 ? sc[nt][2] + b1.x : -1e30f;
            sc[nt][3] = v1 ? sc[nt][3] + b1.y : -1e30f;
            nx0 = fmaxf(nx0, fmaxf(sc[nt][0], sc[nt][1]));
            nx1 = fmaxf(nx1, fmaxf(sc[nt][2], sc[nt][3]));
        }
        nx0 = fmaxf(nx0, __shfl_xor_sync(0xffffffffu, nx0, 1));
        nx0 = fmaxf(nx0, __shfl_xor_sync(0xffffffffu, nx0, 2));
        nx1 = fmaxf(nx1, __shfl_xor_sync(0xffffffffu, nx1, 1));
        nx1 = fmaxf(nx1, __shfl_xor_sync(0xffffffffu, nx1, 2));
        float a0 = __expf(rm0 - nx0), a1 = __expf(rm1 - nx1);
        rm0 = nx0; rm1 = nx1;
        float s0 = 0.f, s1 = 0.f;
#pragma unroll
        for (int nt = 0; nt < 8; nt++) {
            sc[nt][0] = __expf(sc[nt][0] - nx0);
            sc[nt][1] = __expf(sc[nt][1] - nx0);
            sc[nt][2] = __expf(sc[nt][2] - nx1);
            sc[nt][3] = __expf(sc[nt][3] - nx1);
            s0 += sc[nt][0] + sc[nt][1];
            s1 += sc[nt][2] + sc[nt][3];
        }
        s0 += __shfl_xor_sync(0xffffffffu, s0, 1);
        s0 += __shfl_xor_sync(0xffffffffu, s0, 2);
        s1 += __shfl_xor_sync(0xffffffffu, s1, 1);
        s1 += __shfl_xor_sync(0xffffffffu, s1, 2);
        rl0 = rl0 * a0 + s0;
        rl1 = rl1 * a1 + s1;
#pragma unroll
        for (int nt = 0; nt < 8; nt++) {
            o[nt][0] *= a0; o[nt][1] *= a0; o[nt][2] *= a1; o[nt][3] *= a1;
        }

        // ---- O += P V (single fp16 MMA pass, validated R15) ----
        uint32_t vb = kb + 8192;
#pragma unroll
        for (int ks = 0; ks < 4; ks++) {
            uint32_t ph[4];
            ph[0] = packh2(sc[2 * ks][0],     sc[2 * ks][1]);
            ph[1] = packh2(sc[2 * ks][2],     sc[2 * ks][3]);
            ph[2] = packh2(sc[2 * ks + 1][0], sc[2 * ks + 1][1]);
            ph[3] = packh2(sc[2 * ks + 1][2], sc[2 * ks + 1][3]);

            uint32_t bf[8][2];
#pragma unroll
            for (int dp = 0; dp < 4; dp++) {
                int row = ks * 16 + (qq & 1) * 8 + r;
                int cc = dp * 2 + (qq >> 1);
                uint32_t tt[4];
                ldsm4t(tt, vb + row * 128 + ((cc ^ (row & 7)) << 4));
                bf[2 * dp][0] = tt[0]; bf[2 * dp][1] = tt[1];
                bf[2 * dp + 1][0] = tt[2]; bf[2 * dp + 1][1] = tt[3];
            }
#pragma unroll
            for (int nt = 0; nt < 8; nt++)
                mma16816h(o[nt], ph, bf[nt]);
        }
    }

    // ---- finalize + store ----
    float i0 = 1.f / rl0, i1 = 1.f / rl1;
#pragma unroll
    for (int nt = 0; nt < 8; nt++) {
        int dc = h * HD_ + nt * 8 + 2 * t;
        if (rq0 < S_)
            *(float2*)&out[((size_t)b * S_ + rq0) * D_ + dc] =
                make_float2(o[nt][0] * i0, o[nt][1] * i0);
        if (rq1 < S_)
            *(float2*)&out[((size_t)b * S_ + rq1) * D_ + dc] =
                make_float2(o[nt][2] * i1, o[nt][3] * i1);
    }
}

// ---------------------------------------------------------------------------
extern "C" void kernel_launch(void* const* d_in, const int* in_sizes, int n_in,
                              void* d_out, int out_size)
{
    const float* hidden = (const float*)d_in[0];
    const float* bias   = (const float*)d_in[1];
    const float* Wq     = (const float*)d_in[2];
    const float* bq     = (const float*)d_in[3];
    const float* Wk     = (const float*)d_in[4];
    const float* bk     = (const float*)d_in[5];
    const float* Wv     = (const float*)d_in[6];
    const float* bv     = (const float*)d_in[7];
    float* out = (float*)d_out;

    cudaFuncSetAttribute(gemm_kernel,
                         cudaFuncAttributeMaxDynamicSharedMemorySize, GEMM_SMEM);
    cudaFuncSetAttribute(attn_kernel,
                         cudaFuncAttributeMaxDynamicSharedMemorySize, ATT_SMEM);

    convx_kernel<<<(M_PAD * D_ / 4 + 255) / 256, 256>>>(hidden);
    convw_kernel<<<dim3(24, 24, 3), 256>>>(Wq, Wk, Wv);
    {
        size_t tot = (size_t)H_ * S_ * (S_ / 4 + 1);
        convb_kernel<<<(unsigned)((tot + 255) / 256), 256>>>(bias);
    }
    gemm_kernel<<<dim3(65, 12, 3), 128, GEMM_SMEM>>>(bq, bk, bv);

    dim3 g2((S_ + QT - 1) / QT, B_, H_);   // (17, 8, 12)
    attn_kernel<<<g2, 128, ATT_SMEM>>>(out);
}